// round 1
// baseline (speedup 1.0000x reference)
#include <cuda_runtime.h>
#include <cuda_bf16.h>
#include <math_constants.h>

// Problem constants (fixed by setup_inputs)
#define BB 2
#define HH 12
#define SS 2048
#define DD 64
#define BH (BB*HH)            // 24
#define NROWS (BB*HH*SS)      // 49152

// Scratch: normalized Q, K, and mask-premultiplied V
__device__ float g_qn[(size_t)NROWS * DD];
__device__ float g_kn[(size_t)NROWS * DD];
__device__ float g_vm[(size_t)NROWS * DD];

// ---------------------------------------------------------------------------
// Prep kernel: qn = l2norm(Q) rows, kn = l2norm(K) rows, vm = V * mask
// One warp per row (64 elems -> float2 per lane).
// ---------------------------------------------------------------------------
__global__ void __launch_bounds__(256) yoso_prep(
    const float* __restrict__ Q, const float* __restrict__ K,
    const float* __restrict__ V, const float* __restrict__ mask)
{
    int r = blockIdx.x * 8 + threadIdx.y;
    if (r >= NROWS) return;
    int lane = threadIdx.x;
    int s = r % SS;
    int b = r / (HH * SS);
    float m = mask[b * SS + s];
    size_t off = (size_t)r * DD;

    // Q row
    {
        float2 v = *(const float2*)(Q + off + lane * 2);
        float ss = v.x * v.x + v.y * v.y;
        ss += __shfl_xor_sync(0xffffffff, ss, 16);
        ss += __shfl_xor_sync(0xffffffff, ss, 8);
        ss += __shfl_xor_sync(0xffffffff, ss, 4);
        ss += __shfl_xor_sync(0xffffffff, ss, 2);
        ss += __shfl_xor_sync(0xffffffff, ss, 1);
        float inv = 1.0f / fmaxf(sqrtf(ss), 1e-12f);
        float2 o; o.x = v.x * inv; o.y = v.y * inv;
        *(float2*)(g_qn + off + lane * 2) = o;
    }
    // K row
    {
        float2 v = *(const float2*)(K + off + lane * 2);
        float ss = v.x * v.x + v.y * v.y;
        ss += __shfl_xor_sync(0xffffffff, ss, 16);
        ss += __shfl_xor_sync(0xffffffff, ss, 8);
        ss += __shfl_xor_sync(0xffffffff, ss, 4);
        ss += __shfl_xor_sync(0xffffffff, ss, 2);
        ss += __shfl_xor_sync(0xffffffff, ss, 1);
        float inv = 1.0f / fmaxf(sqrtf(ss), 1e-12f);
        float2 o; o.x = v.x * inv; o.y = v.y * inv;
        *(float2*)(g_kn + off + lane * 2) = o;
    }
    // V * mask
    {
        float2 v = *(const float2*)(V + off + lane * 2);
        float2 o; o.x = v.x * m; o.y = v.y * m;
        *(float2*)(g_vm + off + lane * 2) = o;
    }
}

// ---------------------------------------------------------------------------
// Main kernel: per (b,h), tile 64 query rows per block.
//   dots = qn @ kn^T (64x64 per key tile), W = (1 - acos(dots)/pi)^8,
//   acc += W @ vm, epilogue: query-mask, l2norm, + depthwise conv3(vm).
// smem layouts (stride 68 for [k][row] transposed buffers):
//   sQT[k][row], sKT[k][key], sWT[key][row], sV[key][d]
// ---------------------------------------------------------------------------
#define TSTRIDE 68
#define SMEM_FLOATS (3 * 64 * TSTRIDE + 64 * 64)
#define SMEM_BYTES (SMEM_FLOATS * 4)

__device__ __forceinline__ float yoso_w(float x)
{
    x = fminf(fmaxf(x, -1.0f), 1.0f);
    float t = 1.0f - acosf(x) * 0.31830988618379067f;   // 1/pi
    float t2 = t * t;
    float t4 = t2 * t2;
    return t4 * t4;
}

__global__ void __launch_bounds__(256) yoso_main(
    const float* __restrict__ mask, const float* __restrict__ convw,
    float* __restrict__ out)
{
    extern __shared__ float sm[];
    float* sQT = sm;                    // 64 * 68
    float* sKT = sQT + 64 * TSTRIDE;    // 64 * 68
    float* sWT = sKT + 64 * TSTRIDE;    // 64 * 68
    float* sV  = sWT + 64 * TSTRIDE;    // 64 * 64

    const int tid = threadIdx.x;
    const int tx = tid & 15;
    const int ty = tid >> 4;
    const int bh = blockIdx.y;
    const int h = bh % HH;
    const int b = bh / HH;
    const int row0 = blockIdx.x * 64;
    const size_t base = (size_t)bh * SS * DD;

    // Transposed load of the Q tile: thread owns column k = tid%64,
    // row-groups rg*16 + i*4 .. +3. LDG coalesced per row, STS.128 conflict-free.
    {
        const int k = tid & 63;
        const int rg = tid >> 6;
        const float* qp = g_qn + base + (size_t)row0 * DD + k;
        #pragma unroll
        for (int i = 0; i < 4; ++i) {
            int r0 = rg * 16 + i * 4;
            float4 v;
            v.x = qp[(size_t)(r0 + 0) * DD];
            v.y = qp[(size_t)(r0 + 1) * DD];
            v.z = qp[(size_t)(r0 + 2) * DD];
            v.w = qp[(size_t)(r0 + 3) * DD];
            *(float4*)&sQT[k * TSTRIDE + r0] = v;
        }
    }

    float acc[4][4] = {};

    for (int kt = 0; kt < SS / 64; ++kt) {
        __syncthreads();   // prev GEMM2 done (sKT/sV/sWT free); also covers sQT fill on kt==0? no: see 2nd sync
        const int kbase = kt * 64;

        // K tile transposed
        {
            const int k = tid & 63;
            const int rg = tid >> 6;
            const float* kp = g_kn + base + (size_t)kbase * DD + k;
            #pragma unroll
            for (int i = 0; i < 4; ++i) {
                int r0 = rg * 16 + i * 4;
                float4 v;
                v.x = kp[(size_t)(r0 + 0) * DD];
                v.y = kp[(size_t)(r0 + 1) * DD];
                v.z = kp[(size_t)(r0 + 2) * DD];
                v.w = kp[(size_t)(r0 + 3) * DD];
                *(float4*)&sKT[k * TSTRIDE + r0] = v;
            }
        }
        // V tile row-major
        {
            const float4* vg = (const float4*)(g_vm + base + (size_t)kbase * DD);
            float4* vs = (float4*)sV;
            #pragma unroll
            for (int i = 0; i < 4; ++i)
                vs[tid + i * 256] = vg[tid + i * 256];
        }
        __syncthreads();

        // GEMM1: dots[i][j] = sum_k qn[row0+4ty+i][k] * kn[kbase+4tx+j][k]
        float dots[4][4] = {};
        #pragma unroll
        for (int k = 0; k < 64; ++k) {
            float4 a  = *(const float4*)&sQT[k * TSTRIDE + ty * 4];
            float4 bb = *(const float4*)&sKT[k * TSTRIDE + tx * 4];
            dots[0][0] = fmaf(a.x, bb.x, dots[0][0]);
            dots[0][1] = fmaf(a.x, bb.y, dots[0][1]);
            dots[0][2] = fmaf(a.x, bb.z, dots[0][2]);
            dots[0][3] = fmaf(a.x, bb.w, dots[0][3]);
            dots[1][0] = fmaf(a.y, bb.x, dots[1][0]);
            dots[1][1] = fmaf(a.y, bb.y, dots[1][1]);
            dots[1][2] = fmaf(a.y, bb.z, dots[1][2]);
            dots[1][3] = fmaf(a.y, bb.w, dots[1][3]);
            dots[2][0] = fmaf(a.z, bb.x, dots[2][0]);
            dots[2][1] = fmaf(a.z, bb.y, dots[2][1]);
            dots[2][2] = fmaf(a.z, bb.z, dots[2][2]);
            dots[2][3] = fmaf(a.z, bb.w, dots[2][3]);
            dots[3][0] = fmaf(a.w, bb.x, dots[3][0]);
            dots[3][1] = fmaf(a.w, bb.y, dots[3][1]);
            dots[3][2] = fmaf(a.w, bb.z, dots[3][2]);
            dots[3][3] = fmaf(a.w, bb.w, dots[3][3]);
        }

        // Transform + store W transposed: sWT[key][row]
        #pragma unroll
        for (int j = 0; j < 4; ++j) {
            float4 w;
            w.x = yoso_w(dots[0][j]);
            w.y = yoso_w(dots[1][j]);
            w.z = yoso_w(dots[2][j]);
            w.w = yoso_w(dots[3][j]);
            *(float4*)&sWT[(tx * 4 + j) * TSTRIDE + ty * 4] = w;
        }
        __syncthreads();

        // GEMM2: acc[i][j] += sum_t W[row][t] * vm[t][d]
        #pragma unroll
        for (int t = 0; t < 64; ++t) {
            float4 a  = *(const float4*)&sWT[t * TSTRIDE + ty * 4];
            float4 bb = *(const float4*)&sV[t * 64 + tx * 4];
            acc[0][0] = fmaf(a.x, bb.x, acc[0][0]);
            acc[0][1] = fmaf(a.x, bb.y, acc[0][1]);
            acc[0][2] = fmaf(a.x, bb.z, acc[0][2]);
            acc[0][3] = fmaf(a.x, bb.w, acc[0][3]);
            acc[1][0] = fmaf(a.y, bb.x, acc[1][0]);
            acc[1][1] = fmaf(a.y, bb.y, acc[1][1]);
            acc[1][2] = fmaf(a.y, bb.z, acc[1][2]);
            acc[1][3] = fmaf(a.y, bb.w, acc[1][3]);
            acc[2][0] = fmaf(a.z, bb.x, acc[2][0]);
            acc[2][1] = fmaf(a.z, bb.y, acc[2][1]);
            acc[2][2] = fmaf(a.z, bb.z, acc[2][2]);
            acc[2][3] = fmaf(a.z, bb.w, acc[2][3]);
            acc[3][0] = fmaf(a.w, bb.x, acc[3][0]);
            acc[3][1] = fmaf(a.w, bb.y, acc[3][1]);
            acc[3][2] = fmaf(a.w, bb.z, acc[3][2]);
            acc[3][3] = fmaf(a.w, bb.w, acc[3][3]);
        }
    }

    // Epilogue: query mask, row l2norm, + conv3 over sequence from vm
    const float w0 = convw[h * 3 + 0];
    const float w1 = convw[h * 3 + 1];
    const float w2 = convw[h * 3 + 2];

    #pragma unroll
    for (int i = 0; i < 4; ++i) {
        const int gr = row0 + ty * 4 + i;
        const float mq = mask[b * SS + gr];
        float ss = 0.0f;
        #pragma unroll
        for (int j = 0; j < 4; ++j) {
            acc[i][j] *= mq;
            ss = fmaf(acc[i][j], acc[i][j], ss);
        }
        // lanes sharing a row are a contiguous 16-lane group
        ss += __shfl_xor_sync(0xffffffff, ss, 1);
        ss += __shfl_xor_sync(0xffffffff, ss, 2);
        ss += __shfl_xor_sync(0xffffffff, ss, 4);
        ss += __shfl_xor_sync(0xffffffff, ss, 8);
        const float inv = 1.0f / fmaxf(sqrtf(ss), 1e-12f);

        const float* vrow = g_vm + base + (size_t)gr * DD + tx * 4;
        float4 c1 = *(const float4*)(vrow);
        float4 c0, c2;
        if (gr > 0)      c0 = *(const float4*)(vrow - DD);
        else             c0 = make_float4(0.f, 0.f, 0.f, 0.f);
        if (gr < SS - 1) c2 = *(const float4*)(vrow + DD);
        else             c2 = make_float4(0.f, 0.f, 0.f, 0.f);

        float4 o;
        o.x = fmaf(acc[i][0], inv, w0 * c0.x + w1 * c1.x + w2 * c2.x);
        o.y = fmaf(acc[i][1], inv, w0 * c0.y + w1 * c1.y + w2 * c2.y);
        o.z = fmaf(acc[i][2], inv, w0 * c0.z + w1 * c1.z + w2 * c2.z);
        o.w = fmaf(acc[i][3], inv, w0 * c0.w + w1 * c1.w + w2 * c2.w);
        *(float4*)&out[base + (size_t)gr * DD + tx * 4] = o;
    }
}

// ---------------------------------------------------------------------------
extern "C" void kernel_launch(void* const* d_in, const int* in_sizes, int n_in,
                              void* d_out, int out_size)
{
    const float* Q     = (const float*)d_in[0];
    const float* K     = (const float*)d_in[1];
    const float* V     = (const float*)d_in[2];
    const float* mask  = (const float*)d_in[3];
    const float* convw = (const float*)d_in[4];
    float* out = (float*)d_out;

    yoso_prep<<<NROWS / 8, dim3(32, 8)>>>(Q, K, V, mask);

    cudaFuncSetAttribute(yoso_main, cudaFuncAttributeMaxDynamicSharedMemorySize,
                         SMEM_BYTES);
    dim3 grid(SS / 64, BH);
    yoso_main<<<grid, 256, SMEM_BYTES>>>(mask, convw, out);
}

// round 2
// speedup vs baseline: 1.3052x; 1.3052x over previous
#include <cuda_runtime.h>
#include <cuda_bf16.h>
#include <math_constants.h>

// Problem constants (fixed by setup_inputs)
#define BB 2
#define HH 12
#define SS 2048
#define DD 64
#define BH (BB*HH)            // 24
#define NROWS (BB*HH*SS)      // 49152

// Scratch: normalized Q, K, and mask-premultiplied V
__device__ float g_qn[(size_t)NROWS * DD];
__device__ float g_kn[(size_t)NROWS * DD];
__device__ float g_vm[(size_t)NROWS * DD];

// ---------------------------------------------------------------------------
// packed f32x2 helpers
// ---------------------------------------------------------------------------
typedef unsigned long long ull;

__device__ __forceinline__ void ffma2(ull& d, ull a, ull b)
{
    asm("fma.rn.f32x2 %0, %1, %2, %3;" : "=l"(d) : "l"(a), "l"(b), "l"(d));
}
__device__ __forceinline__ ull pack2(float lo, float hi)
{
    ull r;
    asm("mov.b64 %0, {%1, %2};" : "=l"(r) : "f"(lo), "f"(hi));
    return r;
}
__device__ __forceinline__ void unpack2(ull v, float& lo, float& hi)
{
    asm("mov.b64 {%0, %1}, %2;" : "=f"(lo), "=f"(hi) : "l"(v));
}

// ---------------------------------------------------------------------------
// Prep kernel: qn = l2norm(Q) rows, kn = l2norm(K) rows, vm = V * mask
// ---------------------------------------------------------------------------
__global__ void __launch_bounds__(256) yoso_prep(
    const float* __restrict__ Q, const float* __restrict__ K,
    const float* __restrict__ V, const float* __restrict__ mask)
{
    int r = blockIdx.x * 8 + threadIdx.y;
    if (r >= NROWS) return;
    int lane = threadIdx.x;
    int s = r % SS;
    int b = r / (HH * SS);
    float m = mask[b * SS + s];
    size_t off = (size_t)r * DD;

    {
        float2 v = *(const float2*)(Q + off + lane * 2);
        float ss = v.x * v.x + v.y * v.y;
        ss += __shfl_xor_sync(0xffffffff, ss, 16);
        ss += __shfl_xor_sync(0xffffffff, ss, 8);
        ss += __shfl_xor_sync(0xffffffff, ss, 4);
        ss += __shfl_xor_sync(0xffffffff, ss, 2);
        ss += __shfl_xor_sync(0xffffffff, ss, 1);
        float inv = 1.0f / fmaxf(sqrtf(ss), 1e-12f);
        float2 o; o.x = v.x * inv; o.y = v.y * inv;
        *(float2*)(g_qn + off + lane * 2) = o;
    }
    {
        float2 v = *(const float2*)(K + off + lane * 2);
        float ss = v.x * v.x + v.y * v.y;
        ss += __shfl_xor_sync(0xffffffff, ss, 16);
        ss += __shfl_xor_sync(0xffffffff, ss, 8);
        ss += __shfl_xor_sync(0xffffffff, ss, 4);
        ss += __shfl_xor_sync(0xffffffff, ss, 2);
        ss += __shfl_xor_sync(0xffffffff, ss, 1);
        float inv = 1.0f / fmaxf(sqrtf(ss), 1e-12f);
        float2 o; o.x = v.x * inv; o.y = v.y * inv;
        *(float2*)(g_kn + off + lane * 2) = o;
    }
    {
        float2 v = *(const float2*)(V + off + lane * 2);
        float2 o; o.x = v.x * m; o.y = v.y * m;
        *(float2*)(g_vm + off + lane * 2) = o;
    }
}

// ---------------------------------------------------------------------------
// Fast branchless W(x) = (1 - acos(x)/pi)^8
// acos via 7-term poly (A&S style): x>=0: acos = sqrt(1-x)*p(x)
//                                   x<0 : acos = pi - sqrt(1+x)*p(-x)
// => t = 1 - acos/pi = (x>=0) ? 1 - s*p/pi : s*p/pi  with s=sqrt(1-|x|)
// ---------------------------------------------------------------------------
__device__ __forceinline__ float yoso_w(float x)
{
    x = fminf(fmaxf(x, -1.0f), 1.0f);
    float ax = fabsf(x);
    float p = -0.0012624911f;
    p = fmaf(p, ax,  0.0066700901f);
    p = fmaf(p, ax, -0.0170881256f);
    p = fmaf(p, ax,  0.0308918810f);
    p = fmaf(p, ax, -0.0501743046f);
    p = fmaf(p, ax,  0.0889789874f);
    p = fmaf(p, ax, -0.2145988016f);
    p = fmaf(p, ax,  1.5707963050f);
    float s;
    asm("sqrt.approx.f32 %0, %1;" : "=f"(s) : "f"(1.0f - ax));
    float u = s * p * 0.31830988618379067f;   // acos(|x|-branch)/pi
    float t = (x >= 0.0f) ? (1.0f - u) : u;
    float t2 = t * t;
    float t4 = t2 * t2;
    return t4 * t4;
}

// ---------------------------------------------------------------------------
// Main kernel: 128 query rows per block, 64-key tiles, 256 threads.
// Thread tile 8 rows x 4 cols, packed f32x2 FMAs (row pairs).
// smem: sQT[k][row] (RS=132), sKT[k][key] (68), sWT[key][row] (132), sV[key][d] (64)
// ---------------------------------------------------------------------------
#define RS 132
#define KS 68
#define OFF_QT 0
#define OFF_KT (64 * RS)                  // 8448
#define OFF_WT (OFF_KT + 64 * KS)         // 12800
#define OFF_V  (OFF_WT + 64 * RS)         // 21248
#define SMEM_FLOATS (OFF_V + 64 * 64)     // 25344
#define SMEM_BYTES (SMEM_FLOATS * 4)      // 101376

__global__ void __launch_bounds__(256, 2) yoso_main(
    const float* __restrict__ mask, const float* __restrict__ convw,
    float* __restrict__ out)
{
    extern __shared__ float sm[];
    float* sQT = sm + OFF_QT;
    float* sKT = sm + OFF_KT;
    float* sWT = sm + OFF_WT;
    float* sV  = sm + OFF_V;

    const int tid = threadIdx.x;
    const int tx = tid & 15;          // cols / keys group (x4)
    const int ty = tid >> 4;          // rows group (x8)
    const int bh = blockIdx.y;
    const int h = bh % HH;
    const int b = bh / HH;
    const int row0 = blockIdx.x * 128;
    const size_t base = (size_t)bh * SS * DD;

    // ---- fill sQT[k][row] (transposed), 128 rows x 64 k ----
    {
        const int k = tid & 63;
        const int rg = tid >> 6;      // 0..3, each handles 32 rows
        const float* qp = g_qn + base + (size_t)row0 * DD + k;
        #pragma unroll
        for (int i = 0; i < 8; ++i) {
            int r0 = rg * 32 + i * 4;
            float4 v;
            v.x = qp[(size_t)(r0 + 0) * DD];
            v.y = qp[(size_t)(r0 + 1) * DD];
            v.z = qp[(size_t)(r0 + 2) * DD];
            v.w = qp[(size_t)(r0 + 3) * DD];
            *(float4*)&sQT[k * RS + r0] = v;
        }
    }

    ull acc2[4][4];                   // rows pairs (8 rows) x 4 cols
    #pragma unroll
    for (int i = 0; i < 4; ++i)
        #pragma unroll
        for (int j = 0; j < 4; ++j) acc2[i][j] = 0ull;

    for (int kt = 0; kt < SS / 64; ++kt) {
        __syncthreads();              // sWT/sKT/sV free; covers sQT fill on kt=0
        const int kbase = kt * 64;

        // K tile transposed: sKT[k][key]
        {
            const int k = tid & 63;
            const int rg = tid >> 6;
            const float* kp = g_kn + base + (size_t)kbase * DD + k;
            #pragma unroll
            for (int i = 0; i < 4; ++i) {
                int r0 = rg * 16 + i * 4;
                float4 v;
                v.x = kp[(size_t)(r0 + 0) * DD];
                v.y = kp[(size_t)(r0 + 1) * DD];
                v.z = kp[(size_t)(r0 + 2) * DD];
                v.w = kp[(size_t)(r0 + 3) * DD];
                *(float4*)&sKT[k * KS + r0] = v;
            }
        }
        // V tile row-major
        {
            const float4* vg = (const float4*)(g_vm + base + (size_t)kbase * DD);
            float4* vs = (float4*)sV;
            #pragma unroll
            for (int i = 0; i < 4; ++i)
                vs[tid + i * 256] = vg[tid + i * 256];
        }
        __syncthreads();

        // ---- GEMM1: dots (8 rows x 4 keys), packed row pairs ----
        ull d2[4][4];
        #pragma unroll
        for (int i = 0; i < 4; ++i)
            #pragma unroll
            for (int j = 0; j < 4; ++j) d2[i][j] = 0ull;

        #pragma unroll 8
        for (int k = 0; k < 64; ++k) {
            ulonglong2 a01 = *(const ulonglong2*)&sQT[k * RS + ty * 8];
            ulonglong2 a23 = *(const ulonglong2*)&sQT[k * RS + ty * 8 + 4];
            float4 bf = *(const float4*)&sKT[k * KS + tx * 4];
            ull b0 = pack2(bf.x, bf.x);
            ull b1 = pack2(bf.y, bf.y);
            ull b2 = pack2(bf.z, bf.z);
            ull b3 = pack2(bf.w, bf.w);
            ffma2(d2[0][0], a01.x, b0); ffma2(d2[0][1], a01.x, b1);
            ffma2(d2[0][2], a01.x, b2); ffma2(d2[0][3], a01.x, b3);
            ffma2(d2[1][0], a01.y, b0); ffma2(d2[1][1], a01.y, b1);
            ffma2(d2[1][2], a01.y, b2); ffma2(d2[1][3], a01.y, b3);
            ffma2(d2[2][0], a23.x, b0); ffma2(d2[2][1], a23.x, b1);
            ffma2(d2[2][2], a23.x, b2); ffma2(d2[2][3], a23.x, b3);
            ffma2(d2[3][0], a23.y, b0); ffma2(d2[3][1], a23.y, b1);
            ffma2(d2[3][2], a23.y, b2); ffma2(d2[3][3], a23.y, b3);
        }

        // ---- transform + store W transposed: sWT[key][row] ----
        #pragma unroll
        for (int j = 0; j < 4; ++j) {
            float w[8];
            #pragma unroll
            for (int i2 = 0; i2 < 4; ++i2) {
                float lo, hi;
                unpack2(d2[i2][j], lo, hi);
                w[2 * i2]     = yoso_w(lo);
                w[2 * i2 + 1] = yoso_w(hi);
            }
            float* wp = &sWT[(tx * 4 + j) * RS + ty * 8];
            *(float4*)wp       = make_float4(w[0], w[1], w[2], w[3]);
            *(float4*)(wp + 4) = make_float4(w[4], w[5], w[6], w[7]);
        }
        __syncthreads();

        // ---- GEMM2: acc += W @ V, 8 rows x 4 cols ----
        #pragma unroll 8
        for (int t = 0; t < 64; ++t) {
            ulonglong2 a01 = *(const ulonglong2*)&sWT[t * RS + ty * 8];
            ulonglong2 a23 = *(const ulonglong2*)&sWT[t * RS + ty * 8 + 4];
            float4 bf = *(const float4*)&sV[t * 64 + tx * 4];
            ull b0 = pack2(bf.x, bf.x);
            ull b1 = pack2(bf.y, bf.y);
            ull b2 = pack2(bf.z, bf.z);
            ull b3 = pack2(bf.w, bf.w);
            ffma2(acc2[0][0], a01.x, b0); ffma2(acc2[0][1], a01.x, b1);
            ffma2(acc2[0][2], a01.x, b2); ffma2(acc2[0][3], a01.x, b3);
            ffma2(acc2[1][0], a01.y, b0); ffma2(acc2[1][1], a01.y, b1);
            ffma2(acc2[1][2], a01.y, b2); ffma2(acc2[1][3], a01.y, b3);
            ffma2(acc2[2][0], a23.x, b0); ffma2(acc2[2][1], a23.x, b1);
            ffma2(acc2[2][2], a23.x, b2); ffma2(acc2[2][3], a23.x, b3);
            ffma2(acc2[3][0], a23.y, b0); ffma2(acc2[3][1], a23.y, b1);
            ffma2(acc2[3][2], a23.y, b2); ffma2(acc2[3][3], a23.y, b3);
        }
    }

    // ---- epilogue: query mask, row l2norm, + conv3(vm) ----
    const float w0 = convw[h * 3 + 0];
    const float w1 = convw[h * 3 + 1];
    const float w2 = convw[h * 3 + 2];

    #pragma unroll
    for (int i = 0; i < 8; ++i) {
        const int gr = row0 + ty * 8 + i;
        const float mq = mask[b * SS + gr];
        float a[4];
        #pragma unroll
        for (int j = 0; j < 4; ++j) {
            float lo, hi;
            unpack2(acc2[i >> 1][j], lo, hi);
            a[j] = ((i & 1) ? hi : lo) * mq;
        }
        float ss = 0.0f;
        #pragma unroll
        for (int j = 0; j < 4; ++j) ss = fmaf(a[j], a[j], ss);
        ss += __shfl_xor_sync(0xffffffff, ss, 1);
        ss += __shfl_xor_sync(0xffffffff, ss, 2);
        ss += __shfl_xor_sync(0xffffffff, ss, 4);
        ss += __shfl_xor_sync(0xffffffff, ss, 8);
        const float inv = 1.0f / fmaxf(sqrtf(ss), 1e-12f);

        const float* vrow = g_vm + base + (size_t)gr * DD + tx * 4;
        float4 c1 = *(const float4*)(vrow);
        float4 c0, c2;
        if (gr > 0)      c0 = *(const float4*)(vrow - DD);
        else             c0 = make_float4(0.f, 0.f, 0.f, 0.f);
        if (gr < SS - 1) c2 = *(const float4*)(vrow + DD);
        else             c2 = make_float4(0.f, 0.f, 0.f, 0.f);

        float4 o;
        o.x = fmaf(a[0], inv, w0 * c0.x + w1 * c1.x + w2 * c2.x);
        o.y = fmaf(a[1], inv, w0 * c0.y + w1 * c1.y + w2 * c2.y);
        o.z = fmaf(a[2], inv, w0 * c0.z + w1 * c1.z + w2 * c2.z);
        o.w = fmaf(a[3], inv, w0 * c0.w + w1 * c1.w + w2 * c2.w);
        *(float4*)&out[base + (size_t)gr * DD + tx * 4] = o;
    }
}

// ---------------------------------------------------------------------------
extern "C" void kernel_launch(void* const* d_in, const int* in_sizes, int n_in,
                              void* d_out, int out_size)
{
    const float* Q     = (const float*)d_in[0];
    const float* K     = (const float*)d_in[1];
    const float* V     = (const float*)d_in[2];
    const float* mask  = (const float*)d_in[3];
    const float* convw = (const float*)d_in[4];
    float* out = (float*)d_out;

    yoso_prep<<<NROWS / 8, dim3(32, 8)>>>(Q, K, V, mask);

    cudaFuncSetAttribute(yoso_main, cudaFuncAttributeMaxDynamicSharedMemorySize,
                         SMEM_BYTES);
    dim3 grid(SS / 128, BH);
    yoso_main<<<grid, 256, SMEM_BYTES>>>(mask, convw, out);
}

// round 3
// speedup vs baseline: 1.3093x; 1.0031x over previous
#include <cuda_runtime.h>
#include <cuda_bf16.h>
#include <math_constants.h>

// Problem constants (fixed by setup_inputs)
#define BB 2
#define HH 12
#define SS 2048
#define DD 64
#define BH (BB*HH)            // 24
#define NROWS (BB*HH*SS)      // 49152

// Scratch: normalized Q, K, and mask-premultiplied V
__device__ float g_qn[(size_t)NROWS * DD];
__device__ float g_kn[(size_t)NROWS * DD];
__device__ float g_vm[(size_t)NROWS * DD];

// ---------------------------------------------------------------------------
// packed f32x2 helpers
// ---------------------------------------------------------------------------
typedef unsigned long long ull;

__device__ __forceinline__ void ffma2(ull& d, ull a, ull b)
{
    asm("fma.rn.f32x2 %0, %1, %2, %3;" : "=l"(d) : "l"(a), "l"(b), "l"(d));
}
__device__ __forceinline__ ull pack2(float lo, float hi)
{
    ull r;
    asm("mov.b64 %0, {%1, %2};" : "=l"(r) : "f"(lo), "f"(hi));
    return r;
}
__device__ __forceinline__ void unpack2(ull v, float& lo, float& hi)
{
    asm("mov.b64 {%0, %1}, %2;" : "=f"(lo), "=f"(hi) : "l"(v));
}

// ---------------------------------------------------------------------------
// Prep kernel: qn = l2norm(Q) rows, kn = l2norm(K) rows, vm = V * mask
// ---------------------------------------------------------------------------
__global__ void __launch_bounds__(256) yoso_prep(
    const float* __restrict__ Q, const float* __restrict__ K,
    const float* __restrict__ V, const float* __restrict__ mask)
{
    int r = blockIdx.x * 8 + threadIdx.y;
    if (r >= NROWS) return;
    int lane = threadIdx.x;
    int s = r % SS;
    int b = r / (HH * SS);
    float m = mask[b * SS + s];
    size_t off = (size_t)r * DD;

    {
        float2 v = *(const float2*)(Q + off + lane * 2);
        float ss = v.x * v.x + v.y * v.y;
        ss += __shfl_xor_sync(0xffffffff, ss, 16);
        ss += __shfl_xor_sync(0xffffffff, ss, 8);
        ss += __shfl_xor_sync(0xffffffff, ss, 4);
        ss += __shfl_xor_sync(0xffffffff, ss, 2);
        ss += __shfl_xor_sync(0xffffffff, ss, 1);
        float inv = 1.0f / fmaxf(sqrtf(ss), 1e-12f);
        float2 o; o.x = v.x * inv; o.y = v.y * inv;
        *(float2*)(g_qn + off + lane * 2) = o;
    }
    {
        float2 v = *(const float2*)(K + off + lane * 2);
        float ss = v.x * v.x + v.y * v.y;
        ss += __shfl_xor_sync(0xffffffff, ss, 16);
        ss += __shfl_xor_sync(0xffffffff, ss, 8);
        ss += __shfl_xor_sync(0xffffffff, ss, 4);
        ss += __shfl_xor_sync(0xffffffff, ss, 2);
        ss += __shfl_xor_sync(0xffffffff, ss, 1);
        float inv = 1.0f / fmaxf(sqrtf(ss), 1e-12f);
        float2 o; o.x = v.x * inv; o.y = v.y * inv;
        *(float2*)(g_kn + off + lane * 2) = o;
    }
    {
        float2 v = *(const float2*)(V + off + lane * 2);
        float2 o; o.x = v.x * m; o.y = v.y * m;
        *(float2*)(g_vm + off + lane * 2) = o;
    }
}

// ---------------------------------------------------------------------------
// Fast branchless W(x) = (1 - acos(x)/pi)^8
// acos via 7-term poly (A&S style): x>=0: acos = sqrt(1-x)*p(x)
//                                   x<0 : acos = pi - sqrt(1+x)*p(-x)
// => t = 1 - acos/pi = (x>=0) ? 1 - s*p/pi : s*p/pi  with s=sqrt(1-|x|)
// ---------------------------------------------------------------------------
__device__ __forceinline__ float yoso_w(float x)
{
    x = fminf(fmaxf(x, -1.0f), 1.0f);
    float ax = fabsf(x);
    float p = -0.0012624911f;
    p = fmaf(p, ax,  0.0066700901f);
    p = fmaf(p, ax, -0.0170881256f);
    p = fmaf(p, ax,  0.0308918810f);
    p = fmaf(p, ax, -0.0501743046f);
    p = fmaf(p, ax,  0.0889789874f);
    p = fmaf(p, ax, -0.2145988016f);
    p = fmaf(p, ax,  1.5707963050f);
    float s;
    asm("sqrt.approx.f32 %0, %1;" : "=f"(s) : "f"(1.0f - ax));
    float u = s * p * 0.31830988618379067f;   // acos(|x|-branch)/pi
    float t = (x >= 0.0f) ? (1.0f - u) : u;
    float t2 = t * t;
    float t4 = t2 * t2;
    return t4 * t4;
}

// ---------------------------------------------------------------------------
// Main kernel: 128 query rows per block, 64-key tiles, 256 threads.
// Thread tile 8 rows x 4 cols, packed f32x2 FMAs (row pairs).
// smem: sQT[k][row] (RS=132), sKT[k][key] (68), sWT[key][row] (132), sV[key][d] (64)
// ---------------------------------------------------------------------------
#define RS 132
#define KS 68
#define OFF_QT 0
#define OFF_KT (64 * RS)                  // 8448
#define OFF_WT (OFF_KT + 64 * KS)         // 12800
#define OFF_V  (OFF_WT + 64 * RS)         // 21248
#define SMEM_FLOATS (OFF_V + 64 * 64)     // 25344
#define SMEM_BYTES (SMEM_FLOATS * 4)      // 101376

__global__ void __launch_bounds__(256, 2) yoso_main(
    const float* __restrict__ mask, const float* __restrict__ convw,
    float* __restrict__ out)
{
    extern __shared__ float sm[];
    float* sQT = sm + OFF_QT;
    float* sKT = sm + OFF_KT;
    float* sWT = sm + OFF_WT;
    float* sV  = sm + OFF_V;

    const int tid = threadIdx.x;
    const int tx = tid & 15;          // cols / keys group (x4)
    const int ty = tid >> 4;          // rows group (x8)
    const int bh = blockIdx.y;
    const int h = bh % HH;
    const int b = bh / HH;
    const int row0 = blockIdx.x * 128;
    const size_t base = (size_t)bh * SS * DD;

    // ---- fill sQT[k][row] (transposed), 128 rows x 64 k ----
    {
        const int k = tid & 63;
        const int rg = tid >> 6;      // 0..3, each handles 32 rows
        const float* qp = g_qn + base + (size_t)row0 * DD + k;
        #pragma unroll
        for (int i = 0; i < 8; ++i) {
            int r0 = rg * 32 + i * 4;
            float4 v;
            v.x = qp[(size_t)(r0 + 0) * DD];
            v.y = qp[(size_t)(r0 + 1) * DD];
            v.z = qp[(size_t)(r0 + 2) * DD];
            v.w = qp[(size_t)(r0 + 3) * DD];
            *(float4*)&sQT[k * RS + r0] = v;
        }
    }

    ull acc2[4][4];                   // rows pairs (8 rows) x 4 cols
    #pragma unroll
    for (int i = 0; i < 4; ++i)
        #pragma unroll
        for (int j = 0; j < 4; ++j) acc2[i][j] = 0ull;

    for (int kt = 0; kt < SS / 64; ++kt) {
        __syncthreads();              // sWT/sKT/sV free; covers sQT fill on kt=0
        const int kbase = kt * 64;

        // K tile transposed: sKT[k][key]
        {
            const int k = tid & 63;
            const int rg = tid >> 6;
            const float* kp = g_kn + base + (size_t)kbase * DD + k;
            #pragma unroll
            for (int i = 0; i < 4; ++i) {
                int r0 = rg * 16 + i * 4;
                float4 v;
                v.x = kp[(size_t)(r0 + 0) * DD];
                v.y = kp[(size_t)(r0 + 1) * DD];
                v.z = kp[(size_t)(r0 + 2) * DD];
                v.w = kp[(size_t)(r0 + 3) * DD];
                *(float4*)&sKT[k * KS + r0] = v;
            }
        }
        // V tile row-major
        {
            const float4* vg = (const float4*)(g_vm + base + (size_t)kbase * DD);
            float4* vs = (float4*)sV;
            #pragma unroll
            for (int i = 0; i < 4; ++i)
                vs[tid + i * 256] = vg[tid + i * 256];
        }
        __syncthreads();

        // ---- GEMM1: dots (8 rows x 4 keys), packed row pairs ----
        ull d2[4][4];
        #pragma unroll
        for (int i = 0; i < 4; ++i)
            #pragma unroll
            for (int j = 0; j < 4; ++j) d2[i][j] = 0ull;

        #pragma unroll 8
        for (int k = 0; k < 64; ++k) {
            ulonglong2 a01 = *(const ulonglong2*)&sQT[k * RS + ty * 8];
            ulonglong2 a23 = *(const ulonglong2*)&sQT[k * RS + ty * 8 + 4];
            float4 bf = *(const float4*)&sKT[k * KS + tx * 4];
            ull b0 = pack2(bf.x, bf.x);
            ull b1 = pack2(bf.y, bf.y);
            ull b2 = pack2(bf.z, bf.z);
            ull b3 = pack2(bf.w, bf.w);
            ffma2(d2[0][0], a01.x, b0); ffma2(d2[0][1], a01.x, b1);
            ffma2(d2[0][2], a01.x, b2); ffma2(d2[0][3], a01.x, b3);
            ffma2(d2[1][0], a01.y, b0); ffma2(d2[1][1], a01.y, b1);
            ffma2(d2[1][2], a01.y, b2); ffma2(d2[1][3], a01.y, b3);
            ffma2(d2[2][0], a23.x, b0); ffma2(d2[2][1], a23.x, b1);
            ffma2(d2[2][2], a23.x, b2); ffma2(d2[2][3], a23.x, b3);
            ffma2(d2[3][0], a23.y, b0); ffma2(d2[3][1], a23.y, b1);
            ffma2(d2[3][2], a23.y, b2); ffma2(d2[3][3], a23.y, b3);
        }

        // ---- transform + store W transposed: sWT[key][row] ----
        #pragma unroll
        for (int j = 0; j < 4; ++j) {
            float w[8];
            #pragma unroll
            for (int i2 = 0; i2 < 4; ++i2) {
                float lo, hi;
                unpack2(d2[i2][j], lo, hi);
                w[2 * i2]     = yoso_w(lo);
                w[2 * i2 + 1] = yoso_w(hi);
            }
            float* wp = &sWT[(tx * 4 + j) * RS + ty * 8];
            *(float4*)wp       = make_float4(w[0], w[1], w[2], w[3]);
            *(float4*)(wp + 4) = make_float4(w[4], w[5], w[6], w[7]);
        }
        __syncthreads();

        // ---- GEMM2: acc += W @ V, 8 rows x 4 cols ----
        #pragma unroll 8
        for (int t = 0; t < 64; ++t) {
            ulonglong2 a01 = *(const ulonglong2*)&sWT[t * RS + ty * 8];
            ulonglong2 a23 = *(const ulonglong2*)&sWT[t * RS + ty * 8 + 4];
            float4 bf = *(const float4*)&sV[t * 64 + tx * 4];
            ull b0 = pack2(bf.x, bf.x);
            ull b1 = pack2(bf.y, bf.y);
            ull b2 = pack2(bf.z, bf.z);
            ull b3 = pack2(bf.w, bf.w);
            ffma2(acc2[0][0], a01.x, b0); ffma2(acc2[0][1], a01.x, b1);
            ffma2(acc2[0][2], a01.x, b2); ffma2(acc2[0][3], a01.x, b3);
            ffma2(acc2[1][0], a01.y, b0); ffma2(acc2[1][1], a01.y, b1);
            ffma2(acc2[1][2], a01.y, b2); ffma2(acc2[1][3], a01.y, b3);
            ffma2(acc2[2][0], a23.x, b0); ffma2(acc2[2][1], a23.x, b1);
            ffma2(acc2[2][2], a23.x, b2); ffma2(acc2[2][3], a23.x, b3);
            ffma2(acc2[3][0], a23.y, b0); ffma2(acc2[3][1], a23.y, b1);
            ffma2(acc2[3][2], a23.y, b2); ffma2(acc2[3][3], a23.y, b3);
        }
    }

    // ---- epilogue: query mask, row l2norm, + conv3(vm) ----
    const float w0 = convw[h * 3 + 0];
    const float w1 = convw[h * 3 + 1];
    const float w2 = convw[h * 3 + 2];

    #pragma unroll
    for (int i = 0; i < 8; ++i) {
        const int gr = row0 + ty * 8 + i;
        const float mq = mask[b * SS + gr];
        float a[4];
        #pragma unroll
        for (int j = 0; j < 4; ++j) {
            float lo, hi;
            unpack2(acc2[i >> 1][j], lo, hi);
            a[j] = ((i & 1) ? hi : lo) * mq;
        }
        float ss = 0.0f;
        #pragma unroll
        for (int j = 0; j < 4; ++j) ss = fmaf(a[j], a[j], ss);
        ss += __shfl_xor_sync(0xffffffff, ss, 1);
        ss += __shfl_xor_sync(0xffffffff, ss, 2);
        ss += __shfl_xor_sync(0xffffffff, ss, 4);
        ss += __shfl_xor_sync(0xffffffff, ss, 8);
        const float inv = 1.0f / fmaxf(sqrtf(ss), 1e-12f);

        const float* vrow = g_vm + base + (size_t)gr * DD + tx * 4;
        float4 c1 = *(const float4*)(vrow);
        float4 c0, c2;
        if (gr > 0)      c0 = *(const float4*)(vrow - DD);
        else             c0 = make_float4(0.f, 0.f, 0.f, 0.f);
        if (gr < SS - 1) c2 = *(const float4*)(vrow + DD);
        else             c2 = make_float4(0.f, 0.f, 0.f, 0.f);

        float4 o;
        o.x = fmaf(a[0], inv, w0 * c0.x + w1 * c1.x + w2 * c2.x);
        o.y = fmaf(a[1], inv, w0 * c0.y + w1 * c1.y + w2 * c2.y);
        o.z = fmaf(a[2], inv, w0 * c0.z + w1 * c1.z + w2 * c2.z);
        o.w = fmaf(a[3], inv, w0 * c0.w + w1 * c1.w + w2 * c2.w);
        *(float4*)&out[base + (size_t)gr * DD + tx * 4] = o;
    }
}

// ---------------------------------------------------------------------------
extern "C" void kernel_launch(void* const* d_in, const int* in_sizes, int n_in,
                              void* d_out, int out_size)
{
    const float* Q     = (const float*)d_in[0];
    const float* K     = (const float*)d_in[1];
    const float* V     = (const float*)d_in[2];
    const float* mask  = (const float*)d_in[3];
    const float* convw = (const float*)d_in[4];
    float* out = (float*)d_out;

    yoso_prep<<<NROWS / 8, dim3(32, 8)>>>(Q, K, V, mask);

    cudaFuncSetAttribute(yoso_main, cudaFuncAttributeMaxDynamicSharedMemorySize,
                         SMEM_BYTES);
    dim3 grid(SS / 128, BH);
    yoso_main<<<grid, 256, SMEM_BYTES>>>(mask, convw, out);
}